// round 1
// baseline (speedup 1.0000x reference)
#include <cuda_runtime.h>
#include <math.h>

#define N_ROWS 32768
#define K_PROTO 1024
#define D_DIM 256

// ---- scratch (device globals per harness rules: no cudaMalloc allowed) ----
__device__ float  g_logits[(size_t)N_ROWS * K_PROTO];   // 128 MB
__device__ float  g_x2[N_ROWS];
__device__ float  g_p2[K_PROTO];
__device__ float  g_part_y [256 * K_PROTO];             // per-block colsum(y_soft)
__device__ float  g_part_lp[256 * K_PROTO];             // per-block colsum(logprob)
__device__ double g_coly [K_PROTO];
__device__ double g_collp[K_PROTO];

// ---------------------------------------------------------------------------
// K0: row squared norms (warp per row).  which=0 -> g_x2, which=1 -> g_p2
// ---------------------------------------------------------------------------
__global__ void rowsq_kernel(const float* __restrict__ src, int rows, int which)
{
    int warp = (blockIdx.x * blockDim.x + threadIdx.x) >> 5;
    int lane = threadIdx.x & 31;
    if (warp >= rows) return;
    const float4* s = (const float4*)(src + (size_t)warp * D_DIM);
    float acc = 0.f;
#pragma unroll
    for (int i = 0; i < 2; ++i) {
        float4 v = __ldg(&s[lane + 32 * i]);
        acc += v.x * v.x + v.y * v.y + v.z * v.z + v.w * v.w;
    }
#pragma unroll
    for (int off = 16; off; off >>= 1)
        acc += __shfl_xor_sync(0xffffffffu, acc, off);
    if (lane == 0) {
        if (which) g_p2[warp] = acc;
        else       g_x2[warp] = acc;
    }
}

// ---------------------------------------------------------------------------
// K1: fp32 SIMT GEMM  dot[m,k] = X[m,:] . P[k,:]  (D=256)
//     fused epilogue: logits = 2*dot - x2[m] - p2[k] + gumbel[m,k]   (TAU=1)
//     CTA tile 128x128, 256 threads, 8x8 microtile, BK=16
// ---------------------------------------------------------------------------
__global__ void __launch_bounds__(256)
gemm_logits_kernel(const float* __restrict__ X, const float* __restrict__ P,
                   const float* __restrict__ G)
{
    __shared__ float As[16][128];
    __shared__ float Bs[16][128];

    const int t  = threadIdx.x;
    const int tx = t & 15;       // col group (n)
    const int ty = t >> 4;       // row group (m)
    const int m0 = blockIdx.y * 128;
    const int n0 = blockIdx.x * 128;

    float acc[8][8];
#pragma unroll
    for (int i = 0; i < 8; ++i)
#pragma unroll
        for (int j = 0; j < 8; ++j) acc[i][j] = 0.f;

    for (int kt = 0; kt < 16; ++kt) {
        // load 128x16 A-tile and B-tile, stored k-major (transposed)
#pragma unroll
        for (int r = 0; r < 2; ++r) {
            int idx = t + 256 * r;          // 0..511
            int row = idx >> 2;             // 0..127
            int c4  = idx & 3;              // float4 within the 16-wide k chunk
            float4 va = __ldg((const float4*)(X + (size_t)(m0 + row) * D_DIM + kt * 16 + c4 * 4));
            As[c4 * 4 + 0][row] = va.x;
            As[c4 * 4 + 1][row] = va.y;
            As[c4 * 4 + 2][row] = va.z;
            As[c4 * 4 + 3][row] = va.w;
            float4 vb = __ldg((const float4*)(P + (size_t)(n0 + row) * D_DIM + kt * 16 + c4 * 4));
            Bs[c4 * 4 + 0][row] = vb.x;
            Bs[c4 * 4 + 1][row] = vb.y;
            Bs[c4 * 4 + 2][row] = vb.z;
            Bs[c4 * 4 + 3][row] = vb.w;
        }
        __syncthreads();
#pragma unroll
        for (int kk = 0; kk < 16; ++kk) {
            float a[8], b[8];
            *(float4*)&a[0] = *(const float4*)&As[kk][ty * 8];
            *(float4*)&a[4] = *(const float4*)&As[kk][ty * 8 + 4];
            *(float4*)&b[0] = *(const float4*)&Bs[kk][tx * 8];
            *(float4*)&b[4] = *(const float4*)&Bs[kk][tx * 8 + 4];
#pragma unroll
            for (int i = 0; i < 8; ++i)
#pragma unroll
                for (int j = 0; j < 8; ++j)
                    acc[i][j] = fmaf(a[i], b[j], acc[i][j]);
        }
        __syncthreads();
    }

    // epilogue: logits = 2*dot + g - x2[row] - p2[col]
    float p2c[8];
#pragma unroll
    for (int j = 0; j < 8; ++j) p2c[j] = g_p2[n0 + tx * 8 + j];

#pragma unroll
    for (int i = 0; i < 8; ++i) {
        int r = m0 + ty * 8 + i;
        float x2r = g_x2[r];
        const float4* Gr = (const float4*)(G + (size_t)r * K_PROTO + n0 + tx * 8);
        float4* Lr = (float4*)(g_logits + (size_t)r * K_PROTO + n0 + tx * 8);
#pragma unroll
        for (int jb = 0; jb < 2; ++jb) {
            float4 g = __ldg(&Gr[jb]);
            float4 o;
            o.x = fmaf(2.f, acc[i][jb * 4 + 0], g.x) - x2r - p2c[jb * 4 + 0];
            o.y = fmaf(2.f, acc[i][jb * 4 + 1], g.y) - x2r - p2c[jb * 4 + 1];
            o.z = fmaf(2.f, acc[i][jb * 4 + 2], g.z) - x2r - p2c[jb * 4 + 2];
            o.w = fmaf(2.f, acc[i][jb * 4 + 3], g.w) - x2r - p2c[jb * 4 + 3];
            Lr[jb] = o;
        }
    }
}

// ---------------------------------------------------------------------------
// K2: per-row softmax stats + argmax + prototype gather + column partial sums.
//     256 blocks x 256 threads; warp handles 16 rows; lane owns fixed columns
//     k = j*128 + lane*4 + t  (j=0..7, t=0..3) for deterministic reg colsums.
// ---------------------------------------------------------------------------
__global__ void __launch_bounds__(256)
softmax_kernel(const float* __restrict__ P, float* __restrict__ out)
{
    const int b    = blockIdx.x;
    const int w    = threadIdx.x >> 5;
    const int lane = threadIdx.x & 31;

    float cy[32], clp[32];
#pragma unroll
    for (int q = 0; q < 32; ++q) { cy[q] = 0.f; clp[q] = 0.f; }

    for (int i = 0; i < 16; ++i) {
        int row = b * 128 + w * 16 + i;
        const float4* L = (const float4*)(g_logits + (size_t)row * K_PROTO);
        float4 v[8];
#pragma unroll
        for (int j = 0; j < 8; ++j) v[j] = __ldg(&L[j * 32 + lane]);

        // max + first-index argmax (matches jnp.argmax tie rule)
        float m = -3.402823466e38f;
        int idx = 0;
#pragma unroll
        for (int j = 0; j < 8; ++j) {
            const float* pv = (const float*)&v[j];
#pragma unroll
            for (int tt = 0; tt < 4; ++tt) {
                float val = pv[tt];
                int k = j * 128 + lane * 4 + tt;
                if (val > m) { m = val; idx = k; }
            }
        }
#pragma unroll
        for (int off = 16; off; off >>= 1) {
            float om = __shfl_xor_sync(0xffffffffu, m, off);
            int   oi = __shfl_xor_sync(0xffffffffu, idx, off);
            if (om > m || (om == m && oi < idx)) { m = om; idx = oi; }
        }

        // sumexp -> lse
        float s = 0.f;
#pragma unroll
        for (int j = 0; j < 8; ++j) {
            const float* pv = (const float*)&v[j];
#pragma unroll
            for (int tt = 0; tt < 4; ++tt) s += expf(pv[tt] - m);
        }
#pragma unroll
        for (int off = 16; off; off >>= 1)
            s += __shfl_xor_sync(0xffffffffu, s, off);
        float lse = m + logf(s);

        // accumulate column sums of y_soft and logprob
#pragma unroll
        for (int j = 0; j < 8; ++j) {
            const float* pv = (const float*)&v[j];
#pragma unroll
            for (int tt = 0; tt < 4; ++tt) {
                float lp = pv[tt] - lse;
                cy [j * 4 + tt] += expf(lp);
                clp[j * 4 + tt] += lp;
            }
        }

        // quantized[row,:] = P[idx,:]  (straight-through one-hot forward)
        const float4* Pr = (const float4*)(P + (size_t)idx * D_DIM);
        float4* Or = (float4*)(out + (size_t)row * D_DIM);
        Or[lane]      = __ldg(&Pr[lane]);
        Or[lane + 32] = __ldg(&Pr[lane + 32]);
    }

    // deterministic cross-warp reduction into block partials
    __shared__ float s_y[1024];
    __shared__ float s_lp[1024];
    for (int q = threadIdx.x; q < 1024; q += 256) { s_y[q] = 0.f; s_lp[q] = 0.f; }
    __syncthreads();
    for (int w2 = 0; w2 < 8; ++w2) {
        if (w == w2) {
#pragma unroll
            for (int j = 0; j < 8; ++j)
#pragma unroll
                for (int tt = 0; tt < 4; ++tt) {
                    int k = j * 128 + lane * 4 + tt;
                    s_y[k]  += cy [j * 4 + tt];
                    s_lp[k] += clp[j * 4 + tt];
                }
        }
        __syncthreads();
    }
    for (int q = threadIdx.x; q < 1024; q += 256) {
        g_part_y [b * 1024 + q] = s_y[q];
        g_part_lp[b * 1024 + q] = s_lp[q];
    }
}

// ---------------------------------------------------------------------------
// K3: reduce 256 block partials per column (double precision, deterministic)
// ---------------------------------------------------------------------------
__global__ void colreduce_kernel()
{
    int k = blockIdx.x * 128 + threadIdx.x;
    double sy = 0.0, slp = 0.0;
    for (int bb = 0; bb < 256; ++bb) {
        sy  += (double)g_part_y [bb * 1024 + k];
        slp += (double)g_part_lp[bb * 1024 + k];
    }
    g_coly[k]  = sy;
    g_collp[k] = slp;
}

// ---------------------------------------------------------------------------
// K4: final scalar: prior, capacity (KL batchmean), entropy -> vq_loss
// capacity = sum_k prior_k*log(prior_k) - sum_k prior_k * colmean_logprob_k
// loss = capacity - 0.001 * ent,   ent = -sum_k prior_k*log(prior_k)
// ---------------------------------------------------------------------------
__global__ void final_kernel(float* __restrict__ out, int out_size)
{
    const int t = threadIdx.x;
    double t1 = 0.0, t2 = 0.0;
    for (int k = t; k < K_PROTO; k += 256) {
        double prior = g_coly[k] * (1.0 / N_ROWS) + 1e-6;
        double cmlp  = g_collp[k] * (1.0 / N_ROWS);
        double lpr   = log(prior);
        t1 += prior * lpr;
        t2 += prior * cmlp;
    }
    __shared__ double r1[256];
    __shared__ double r2[256];
    r1[t] = t1; r2[t] = t2;
    __syncthreads();
    for (int off = 128; off; off >>= 1) {
        if (t < off) { r1[t] += r1[t + off]; r2[t] += r2[t + off]; }
        __syncthreads();
    }
    if (t == 0) {
        double capacity = r1[0] - r2[0];
        double ent      = -r1[0];
        double loss     = capacity - 0.001 * ent;   // KL_WEIGHT = 1
        out[out_size - 1] = (float)loss;
    }
}

// ---------------------------------------------------------------------------
extern "C" void kernel_launch(void* const* d_in, const int* in_sizes, int n_in,
                              void* d_out, int out_size)
{
    const float* X = (const float*)d_in[0];   // latents    [32768,256]
    const float* P = (const float*)d_in[1];   // prototypes [1024,256]
    const float* G = (const float*)d_in[2];   // gumbel     [32768,1024]
    float* out = (float*)d_out;               // [32768*256 quantized][1 loss]

    rowsq_kernel<<<N_ROWS / 8, 256>>>(X, N_ROWS, 0);
    rowsq_kernel<<<K_PROTO / 8, 256>>>(P, K_PROTO, 1);
    gemm_logits_kernel<<<dim3(K_PROTO / 128, N_ROWS / 128), 256>>>(X, P, G);
    softmax_kernel<<<N_ROWS / 128, 256>>>(P, out);
    colreduce_kernel<<<K_PROTO / 128, 128>>>();
    final_kernel<<<1, 256>>>(out, out_size);
}

// round 4
// speedup vs baseline: 1.8489x; 1.8489x over previous
#include <cuda_runtime.h>
#include <cuda_bf16.h>
#include <cstdint>
#include <math.h>

#define N_ROWS 32768
#define K_PROTO 1024
#define D_DIM 256

// ---- scratch (device globals: no cudaMalloc allowed) ----
__device__ float          g_logits[(size_t)N_ROWS * K_PROTO];   // 128 MB
__device__ float          g_x2[N_ROWS];
__device__ float          g_p2[K_PROTO];
__device__ __nv_bfloat16  g_xhi[(size_t)N_ROWS * D_DIM];
__device__ __nv_bfloat16  g_xlo[(size_t)N_ROWS * D_DIM];
__device__ __nv_bfloat16  g_phi[(size_t)K_PROTO * D_DIM];
__device__ __nv_bfloat16  g_plo[(size_t)K_PROTO * D_DIM];
__device__ float          g_part_y[256 * K_PROTO];              // colsum(y_soft) per block
__device__ float          g_part_v[256 * K_PROTO];              // colsum(logits) per block
__device__ double         g_part_lse[256];                      // sum(lse) per block
__device__ double         g_coly[K_PROTO];
__device__ double         g_colv[K_PROTO];

__device__ __forceinline__ uint32_t smem_u32(const void* p) {
    uint32_t a;
    asm("{ .reg .u64 t; cvta.to.shared.u64 t, %1; cvt.u32.u64 %0, t; }"
        : "=r"(a) : "l"(p));
    return a;
}
__device__ __forceinline__ void cp16(uint32_t saddr, const void* g) {
    asm volatile("cp.async.cg.shared.global [%0], [%1], 16;" :: "r"(saddr), "l"(g) : "memory");
}

// ===========================================================================
// K0: fused prep — warp per row: bf16 hi/lo split + row squared norm.
// ===========================================================================
__global__ void prep_kernel(const float* __restrict__ src,
                            __nv_bfloat16* __restrict__ hi,
                            __nv_bfloat16* __restrict__ lo,
                            float* __restrict__ sq, int rows)
{
    int warp = (blockIdx.x * blockDim.x + threadIdx.x) >> 5;
    int lane = threadIdx.x & 31;
    if (warp >= rows) return;
    const float4* s = (const float4*)(src + (size_t)warp * D_DIM);
    uint2* H = (uint2*)(hi + (size_t)warp * D_DIM);
    uint2* L = (uint2*)(lo + (size_t)warp * D_DIM);
    float acc = 0.f;
#pragma unroll
    for (int i = 0; i < 2; ++i) {
        int c = lane + 32 * i;
        float4 v = __ldg(&s[c]);
        acc += v.x * v.x + v.y * v.y + v.z * v.z + v.w * v.w;
        __nv_bfloat16 h0 = __float2bfloat16(v.x), h1 = __float2bfloat16(v.y);
        __nv_bfloat16 h2 = __float2bfloat16(v.z), h3 = __float2bfloat16(v.w);
        __nv_bfloat16 l0 = __float2bfloat16(v.x - __bfloat162float(h0));
        __nv_bfloat16 l1 = __float2bfloat16(v.y - __bfloat162float(h1));
        __nv_bfloat16 l2 = __float2bfloat16(v.z - __bfloat162float(h2));
        __nv_bfloat16 l3 = __float2bfloat16(v.w - __bfloat162float(h3));
        __nv_bfloat162 a; a.x = h0; a.y = h1;
        __nv_bfloat162 b; b.x = h2; b.y = h3;
        uint2 hv; hv.x = *(uint32_t*)&a; hv.y = *(uint32_t*)&b;
        __nv_bfloat162 cpl; cpl.x = l0; cpl.y = l1;
        __nv_bfloat162 dpl; dpl.x = l2; dpl.y = l3;
        uint2 lv; lv.x = *(uint32_t*)&cpl; lv.y = *(uint32_t*)&dpl;
        H[c] = hv;
        L[c] = lv;
    }
#pragma unroll
    for (int off = 16; off; off >>= 1)
        acc += __shfl_xor_sync(0xffffffffu, acc, off);
    if (lane == 0) sq[warp] = acc;
}

// ===========================================================================
// K1: bf16 mma.sync GEMM (3-term split over K_eff=768 in 12 k64 stages)
//     CTA 128x256, 512 threads, warp tile 64x32, cp.async double buffer.
//     epilogue: logits = 2*dot + g - x2[m] - p2[k]
// ===========================================================================
#define MT 128
#define NT 256
#define STAGE_BYTES 49152          // A 16K + B 32K
#define GEMM_SMEM   (2 * STAGE_BYTES)

__device__ __forceinline__ void issue_stage(int c, uint32_t sbase, int m0, int n0, int tid)
{
    const int term = c >> 2;
    const int koff = (c & 3) * 64;
    const __nv_bfloat16* As = (term == 2) ? g_xlo : g_xhi;
    const __nv_bfloat16* Bs = (term == 1) ? g_plo : g_phi;
    const uint32_t bufA = sbase + (uint32_t)(c & 1) * STAGE_BYTES;
    const uint32_t bufB = bufA + 16384;
#pragma unroll
    for (int it = 0; it < 2; ++it) {
        int i = tid + 512 * it, row = i >> 3, cc = i & 7;
        cp16(bufA + row * 128 + ((cc ^ (row & 7)) << 4),
             As + (size_t)(m0 + row) * D_DIM + koff + cc * 8);
    }
#pragma unroll
    for (int it = 0; it < 4; ++it) {
        int i = tid + 512 * it, row = i >> 3, cc = i & 7;
        cp16(bufB + row * 128 + ((cc ^ (row & 7)) << 4),
             Bs + (size_t)(n0 + row) * D_DIM + koff + cc * 8);
    }
    asm volatile("cp.async.commit_group;" ::: "memory");
}

__global__ void __launch_bounds__(512, 1)
gemm_mma_kernel(const float* __restrict__ G)
{
    extern __shared__ __align__(128) char sm[];
    const uint32_t sbase = smem_u32(sm);
    const int tid  = threadIdx.x;
    const int warp = tid >> 5;
    const int lane = tid & 31;
    const int wm   = warp >> 3;          // 0..1
    const int wn   = warp & 7;           // 0..7
    const int m0   = blockIdx.y * MT;
    const int n0   = blockIdx.x * NT;

    float d[4][4][4];
#pragma unroll
    for (int mi = 0; mi < 4; ++mi)
#pragma unroll
        for (int ni = 0; ni < 4; ++ni)
#pragma unroll
            for (int q = 0; q < 4; ++q) d[mi][ni][q] = 0.f;

    issue_stage(0, sbase, m0, n0, tid);
    issue_stage(1, sbase, m0, n0, tid);

    for (int c = 0; c < 12; ++c) {
        if (c < 11) asm volatile("cp.async.wait_group 1;" ::: "memory");
        else        asm volatile("cp.async.wait_group 0;" ::: "memory");
        __syncthreads();
        const uint32_t bufA = sbase + (uint32_t)(c & 1) * STAGE_BYTES;
        const uint32_t bufB = bufA + 16384;
#pragma unroll
        for (int ks = 0; ks < 4; ++ks) {
            uint32_t a[16], br[8];
#pragma unroll
            for (int mi = 0; mi < 4; ++mi) {
                int row = wm * 64 + mi * 16 + (lane & 15);
                int cc  = ks * 2 + (lane >> 4);
                uint32_t ad = bufA + row * 128 + ((cc ^ (row & 7)) << 4);
                asm volatile("ldmatrix.sync.aligned.m8n8.x4.shared.b16 {%0,%1,%2,%3}, [%4];"
                    : "=r"(a[mi*4+0]), "=r"(a[mi*4+1]), "=r"(a[mi*4+2]), "=r"(a[mi*4+3])
                    : "r"(ad));
            }
#pragma unroll
            for (int p = 0; p < 2; ++p) {
                int nrow = wn * 32 + p * 16 + ((lane >> 4) << 3) + (lane & 7);
                int cc   = ks * 2 + ((lane >> 3) & 1);
                uint32_t bd = bufB + nrow * 128 + ((cc ^ (nrow & 7)) << 4);
                asm volatile("ldmatrix.sync.aligned.m8n8.x4.shared.b16 {%0,%1,%2,%3}, [%4];"
                    : "=r"(br[p*4+0]), "=r"(br[p*4+1]), "=r"(br[p*4+2]), "=r"(br[p*4+3])
                    : "r"(bd));
            }
#pragma unroll
            for (int mi = 0; mi < 4; ++mi)
#pragma unroll
                for (int ni = 0; ni < 4; ++ni) {
                    asm volatile(
                        "mma.sync.aligned.m16n8k16.row.col.f32.bf16.bf16.f32 "
                        "{%0,%1,%2,%3}, {%4,%5,%6,%7}, {%8,%9}, {%0,%1,%2,%3};"
                        : "+f"(d[mi][ni][0]), "+f"(d[mi][ni][1]),
                          "+f"(d[mi][ni][2]), "+f"(d[mi][ni][3])
                        : "r"(a[mi*4+0]), "r"(a[mi*4+1]), "r"(a[mi*4+2]), "r"(a[mi*4+3]),
                          "r"(br[ni*2+0]), "r"(br[ni*2+1]));
                }
        }
        __syncthreads();
        if (c + 2 < 12) issue_stage(c + 2, sbase, m0, n0, tid);
    }

    // epilogue
#pragma unroll
    for (int mi = 0; mi < 4; ++mi) {
        int r0 = m0 + wm * 64 + mi * 16 + (lane >> 2);
        float x20 = g_x2[r0], x21 = g_x2[r0 + 8];
#pragma unroll
        for (int ni = 0; ni < 4; ++ni) {
            int col = n0 + wn * 32 + ni * 8 + (lane & 3) * 2;
            float2 p2v = *(const float2*)&g_p2[col];
            float2 ga = __ldg((const float2*)(G + (size_t)r0 * K_PROTO + col));
            float2 gb = __ldg((const float2*)(G + (size_t)(r0 + 8) * K_PROTO + col));
            float2 o0, o1;
            o0.x = fmaf(2.f, d[mi][ni][0], ga.x) - x20 - p2v.x;
            o0.y = fmaf(2.f, d[mi][ni][1], ga.y) - x20 - p2v.y;
            o1.x = fmaf(2.f, d[mi][ni][2], gb.x) - x21 - p2v.x;
            o1.y = fmaf(2.f, d[mi][ni][3], gb.y) - x21 - p2v.y;
            *(float2*)(g_logits + (size_t)r0 * K_PROTO + col) = o0;
            *(float2*)(g_logits + (size_t)(r0 + 8) * K_PROTO + col) = o1;
        }
    }
}

// ===========================================================================
// K2: per-row softmax stats + argmax + gather + column partial sums.
// ===========================================================================
__global__ void __launch_bounds__(256)
softmax_kernel(const float* __restrict__ P, float* __restrict__ out)
{
    const int b    = blockIdx.x;
    const int w    = threadIdx.x >> 5;
    const int lane = threadIdx.x & 31;

    float cy[32], cv[32];
#pragma unroll
    for (int q = 0; q < 32; ++q) { cy[q] = 0.f; cv[q] = 0.f; }
    float lsesum = 0.f;

    for (int i = 0; i < 16; ++i) {
        int row = b * 128 + w * 16 + i;
        const float4* L = (const float4*)(g_logits + (size_t)row * K_PROTO);
        float4 v[8];
#pragma unroll
        for (int j = 0; j < 8; ++j) v[j] = __ldg(&L[j * 32 + lane]);

        float m = -3.402823466e38f;
        int idx = 0;
#pragma unroll
        for (int j = 0; j < 8; ++j) {
            float* pv = (float*)&v[j];
#pragma unroll
            for (int tt = 0; tt < 4; ++tt) {
                float val = pv[tt];
                cv[j * 4 + tt] += val;
                int k = j * 128 + lane * 4 + tt;
                if (val > m) { m = val; idx = k; }
            }
        }
#pragma unroll
        for (int off = 16; off; off >>= 1) {
            float om = __shfl_xor_sync(0xffffffffu, m, off);
            int   oi = __shfl_xor_sync(0xffffffffu, idx, off);
            if (om > m || (om == m && oi < idx)) { m = om; idx = oi; }
        }

        float s = 0.f;
#pragma unroll
        for (int j = 0; j < 8; ++j) {
            float* pv = (float*)&v[j];
#pragma unroll
            for (int tt = 0; tt < 4; ++tt) { pv[tt] = expf(pv[tt] - m); s += pv[tt]; }
        }
#pragma unroll
        for (int off = 16; off; off >>= 1)
            s += __shfl_xor_sync(0xffffffffu, s, off);
        float lse = m + logf(s);
        lsesum += lse;
        float inv = 1.f / s;

#pragma unroll
        for (int j = 0; j < 8; ++j) {
            const float* pv = (const float*)&v[j];
#pragma unroll
            for (int tt = 0; tt < 4; ++tt)
                cy[j * 4 + tt] += pv[tt] * inv;
        }

        const float4* Pr = (const float4*)(P + (size_t)idx * D_DIM);
        float4* Or = (float4*)(out + (size_t)row * D_DIM);
        Or[lane]      = __ldg(&Pr[lane]);
        Or[lane + 32] = __ldg(&Pr[lane + 32]);
    }

    __shared__ float s_y[1024];
    __shared__ float s_v[1024];
    __shared__ float s_lse[8];
    for (int q = threadIdx.x; q < 1024; q += 256) { s_y[q] = 0.f; s_v[q] = 0.f; }
    __syncthreads();
    for (int w2 = 0; w2 < 8; ++w2) {
        if (w == w2) {
#pragma unroll
            for (int j = 0; j < 8; ++j)
#pragma unroll
                for (int tt = 0; tt < 4; ++tt) {
                    int k = j * 128 + lane * 4 + tt;
                    s_y[k] += cy[j * 4 + tt];
                    s_v[k] += cv[j * 4 + tt];
                }
        }
        __syncthreads();
    }
    if (lane == 0) s_lse[w] = lsesum;
    __syncthreads();
    for (int q = threadIdx.x; q < 1024; q += 256) {
        g_part_y[b * 1024 + q] = s_y[q];
        g_part_v[b * 1024 + q] = s_v[q];
    }
    if (threadIdx.x == 0) {
        double t = 0.0;
        for (int q = 0; q < 8; ++q) t += (double)s_lse[q];
        g_part_lse[b] = t;
    }
}

// ===========================================================================
// K3: column reduce block partials (double, deterministic)
// ===========================================================================
__global__ void colreduce_kernel()
{
    int k = blockIdx.x * 128 + threadIdx.x;
    double sy = 0.0, sv = 0.0;
    for (int bb = 0; bb < 256; ++bb) {
        sy += (double)g_part_y[bb * 1024 + k];
        sv += (double)g_part_v[bb * 1024 + k];
    }
    g_coly[k] = sy;
    g_colv[k] = sv;
}

// ===========================================================================
// K4: final scalar
// ===========================================================================
__global__ void final_kernel(float* __restrict__ out, int out_size)
{
    const int t = threadIdx.x;
    double lse_total = 0.0;
    for (int q = 0; q < 256; ++q) lse_total += g_part_lse[q];
    const double lse_mean = lse_total * (1.0 / N_ROWS);

    double t1 = 0.0, t2 = 0.0;
    for (int k = t; k < K_PROTO; k += 256) {
        double prior = g_coly[k] * (1.0 / N_ROWS) + 1e-6;
        double cmlp  = g_colv[k] * (1.0 / N_ROWS) - lse_mean;
        t1 += prior * log(prior);
        t2 += prior * cmlp;
    }
    __shared__ double r1[256];
    __shared__ double r2[256];
    r1[t] = t1; r2[t] = t2;
    __syncthreads();
    for (int off = 128; off; off >>= 1) {
        if (t < off) { r1[t] += r1[t + off]; r2[t] += r2[t + off]; }
        __syncthreads();
    }
    if (t == 0) {
        double capacity = r1[0] - r2[0];
        double ent      = -r1[0];
        out[out_size - 1] = (float)(capacity - 0.001 * ent);
    }
}

// ===========================================================================
extern "C" void kernel_launch(void* const* d_in, const int* in_sizes, int n_in,
                              void* d_out, int out_size)
{
    const float* X = (const float*)d_in[0];   // latents    [32768,256]
    const float* P = (const float*)d_in[1];   // prototypes [1024,256]
    const float* G = (const float*)d_in[2];   // gumbel     [32768,1024]
    float* out = (float*)d_out;

    cudaFuncSetAttribute(gemm_mma_kernel,
                         cudaFuncAttributeMaxDynamicSharedMemorySize, GEMM_SMEM);

    __nv_bfloat16 *xhi, *xlo, *phi, *plo;
    float *x2, *p2;
    cudaGetSymbolAddress((void**)&xhi, g_xhi);
    cudaGetSymbolAddress((void**)&xlo, g_xlo);
    cudaGetSymbolAddress((void**)&phi, g_phi);
    cudaGetSymbolAddress((void**)&plo, g_plo);
    cudaGetSymbolAddress((void**)&x2, g_x2);
    cudaGetSymbolAddress((void**)&p2, g_p2);

    prep_kernel<<<N_ROWS / 8, 256>>>(X, xhi, xlo, x2, N_ROWS);
    prep_kernel<<<K_PROTO / 8, 256>>>(P, phi, plo, p2, K_PROTO);
    gemm_mma_kernel<<<dim3(K_PROTO / NT, N_ROWS / MT), 512, GEMM_SMEM>>>(G);
    softmax_kernel<<<N_ROWS / 128, 256>>>(P, out);
    colreduce_kernel<<<K_PROTO / 128, 128>>>();
    final_kernel<<<1, 256>>>(out, out_size);
}

// round 5
// speedup vs baseline: 1.8757x; 1.0145x over previous
#include <cuda_runtime.h>
#include <cuda_bf16.h>
#include <cstdint>
#include <math.h>

#define N_ROWS 32768
#define K_PROTO 1024
#define D_DIM 256

// ---- scratch (device globals: no cudaMalloc allowed) ----
__device__ float          g_logits[(size_t)N_ROWS * K_PROTO];   // 128 MB
__device__ float          g_x2[N_ROWS];
__device__ float          g_p2[K_PROTO];
__device__ __nv_bfloat16  g_xhi[(size_t)N_ROWS * D_DIM];
__device__ __nv_bfloat16  g_xlo[(size_t)N_ROWS * D_DIM];
__device__ __nv_bfloat16  g_phi[(size_t)K_PROTO * D_DIM];
__device__ __nv_bfloat16  g_plo[(size_t)K_PROTO * D_DIM];
__device__ float          g_part_y[256 * K_PROTO];              // colsum(y_soft) per softmax block
__device__ float          g_vpart[512 * K_PROTO];               // colsum(logits) per (m_block, wm)
__device__ double         g_part_lse[256];                      // sum(lse) per softmax block
__device__ double         g_coly[K_PROTO];
__device__ double         g_colv[K_PROTO];

__device__ __forceinline__ uint32_t smem_u32(const void* p) {
    uint32_t a;
    asm("{ .reg .u64 t; cvta.to.shared.u64 t, %1; cvt.u32.u64 %0, t; }"
        : "=r"(a) : "l"(p));
    return a;
}
__device__ __forceinline__ void cp16(uint32_t saddr, const void* g) {
    asm volatile("cp.async.cg.shared.global [%0], [%1], 16;" :: "r"(saddr), "l"(g) : "memory");
}

// ===========================================================================
// K0: fused prep — warp per row: bf16 hi/lo split + row squared norm.
// ===========================================================================
__global__ void prep_kernel(const float* __restrict__ src,
                            __nv_bfloat16* __restrict__ hi,
                            __nv_bfloat16* __restrict__ lo,
                            float* __restrict__ sq, int rows)
{
    int warp = (blockIdx.x * blockDim.x + threadIdx.x) >> 5;
    int lane = threadIdx.x & 31;
    if (warp >= rows) return;
    const float4* s = (const float4*)(src + (size_t)warp * D_DIM);
    uint2* H = (uint2*)(hi + (size_t)warp * D_DIM);
    uint2* L = (uint2*)(lo + (size_t)warp * D_DIM);
    float acc = 0.f;
#pragma unroll
    for (int i = 0; i < 2; ++i) {
        int c = lane + 32 * i;
        float4 v = __ldg(&s[c]);
        acc += v.x * v.x + v.y * v.y + v.z * v.z + v.w * v.w;
        __nv_bfloat16 h0 = __float2bfloat16(v.x), h1 = __float2bfloat16(v.y);
        __nv_bfloat16 h2 = __float2bfloat16(v.z), h3 = __float2bfloat16(v.w);
        __nv_bfloat16 l0 = __float2bfloat16(v.x - __bfloat162float(h0));
        __nv_bfloat16 l1 = __float2bfloat16(v.y - __bfloat162float(h1));
        __nv_bfloat16 l2 = __float2bfloat16(v.z - __bfloat162float(h2));
        __nv_bfloat16 l3 = __float2bfloat16(v.w - __bfloat162float(h3));
        __nv_bfloat162 a; a.x = h0; a.y = h1;
        __nv_bfloat162 b; b.x = h2; b.y = h3;
        uint2 hv; hv.x = *(uint32_t*)&a; hv.y = *(uint32_t*)&b;
        __nv_bfloat162 cpl; cpl.x = l0; cpl.y = l1;
        __nv_bfloat162 dpl; dpl.x = l2; dpl.y = l3;
        uint2 lv; lv.x = *(uint32_t*)&cpl; lv.y = *(uint32_t*)&dpl;
        H[c] = hv;
        L[c] = lv;
    }
#pragma unroll
    for (int off = 16; off; off >>= 1)
        acc += __shfl_xor_sync(0xffffffffu, acc, off);
    if (lane == 0) sq[warp] = acc;
}

// ===========================================================================
// K1: bf16 mma.sync GEMM (3-term split over K_eff=768 in 12 k64 stages)
//     CTA 128x256, 512 threads, warp tile 64x32.
//     4-stage cp.async pipeline, ONE __syncthreads per stage.
//     epilogue: logits = 2*dot + g - x2[m] - p2[k]; fused colsum(logits).
// ===========================================================================
#define MT 128
#define NT 256
#define STAGE_BYTES 49152          // A 16K + B 32K
#define GEMM_SMEM   (4 * STAGE_BYTES)   // 192 KB

__device__ __forceinline__ void issue_stage(int c, uint32_t sbase, int m0, int n0, int tid)
{
    const int term = c >> 2;
    const int koff = (c & 3) * 64;
    const __nv_bfloat16* As = (term == 2) ? g_xlo : g_xhi;
    const __nv_bfloat16* Bs = (term == 1) ? g_plo : g_phi;
    const uint32_t bufA = sbase + (uint32_t)(c & 3) * STAGE_BYTES;
    const uint32_t bufB = bufA + 16384;
#pragma unroll
    for (int it = 0; it < 2; ++it) {
        int i = tid + 512 * it, row = i >> 3, cc = i & 7;
        cp16(bufA + row * 128 + ((cc ^ (row & 7)) << 4),
             As + (size_t)(m0 + row) * D_DIM + koff + cc * 8);
    }
#pragma unroll
    for (int it = 0; it < 4; ++it) {
        int i = tid + 512 * it, row = i >> 3, cc = i & 7;
        cp16(bufB + row * 128 + ((cc ^ (row & 7)) << 4),
             Bs + (size_t)(n0 + row) * D_DIM + koff + cc * 8);
    }
    asm volatile("cp.async.commit_group;" ::: "memory");
}

__global__ void __launch_bounds__(512, 1)
gemm_mma_kernel(const float* __restrict__ G)
{
    extern __shared__ __align__(128) char sm[];
    const uint32_t sbase = smem_u32(sm);
    const int tid  = threadIdx.x;
    const int warp = tid >> 5;
    const int lane = tid & 31;
    const int wm   = warp >> 3;          // 0..1
    const int wn   = warp & 7;           // 0..7
    const int m0   = blockIdx.y * MT;
    const int n0   = blockIdx.x * NT;

    float d[4][4][4];
#pragma unroll
    for (int mi = 0; mi < 4; ++mi)
#pragma unroll
        for (int ni = 0; ni < 4; ++ni)
#pragma unroll
            for (int q = 0; q < 4; ++q) d[mi][ni][q] = 0.f;

    issue_stage(0, sbase, m0, n0, tid);
    issue_stage(1, sbase, m0, n0, tid);
    issue_stage(2, sbase, m0, n0, tid);

    for (int c = 0; c < 12; ++c) {
        if (c < 10)      asm volatile("cp.async.wait_group 2;" ::: "memory");
        else if (c == 10) asm volatile("cp.async.wait_group 1;" ::: "memory");
        else              asm volatile("cp.async.wait_group 0;" ::: "memory");
        __syncthreads();
        if (c + 3 < 12) issue_stage(c + 3, sbase, m0, n0, tid);

        const uint32_t bufA = sbase + (uint32_t)(c & 3) * STAGE_BYTES;
        const uint32_t bufB = bufA + 16384;
#pragma unroll
        for (int ks = 0; ks < 4; ++ks) {
            uint32_t a[16], br[8];
#pragma unroll
            for (int mi = 0; mi < 4; ++mi) {
                int row = wm * 64 + mi * 16 + (lane & 15);
                int cc  = ks * 2 + (lane >> 4);
                uint32_t ad = bufA + row * 128 + ((cc ^ (row & 7)) << 4);
                asm volatile("ldmatrix.sync.aligned.m8n8.x4.shared.b16 {%0,%1,%2,%3}, [%4];"
                    : "=r"(a[mi*4+0]), "=r"(a[mi*4+1]), "=r"(a[mi*4+2]), "=r"(a[mi*4+3])
                    : "r"(ad));
            }
#pragma unroll
            for (int p = 0; p < 2; ++p) {
                int nrow = wn * 32 + p * 16 + ((lane >> 4) << 3) + (lane & 7);
                int cc   = ks * 2 + ((lane >> 3) & 1);
                uint32_t bd = bufB + nrow * 128 + ((cc ^ (nrow & 7)) << 4);
                asm volatile("ldmatrix.sync.aligned.m8n8.x4.shared.b16 {%0,%1,%2,%3}, [%4];"
                    : "=r"(br[p*4+0]), "=r"(br[p*4+1]), "=r"(br[p*4+2]), "=r"(br[p*4+3])
                    : "r"(bd));
            }
#pragma unroll
            for (int mi = 0; mi < 4; ++mi)
#pragma unroll
                for (int ni = 0; ni < 4; ++ni) {
                    asm volatile(
                        "mma.sync.aligned.m16n8k16.row.col.f32.bf16.bf16.f32 "
                        "{%0,%1,%2,%3}, {%4,%5,%6,%7}, {%8,%9}, {%0,%1,%2,%3};"
                        : "+f"(d[mi][ni][0]), "+f"(d[mi][ni][1]),
                          "+f"(d[mi][ni][2]), "+f"(d[mi][ni][3])
                        : "r"(a[mi*4+0]), "r"(a[mi*4+1]), "r"(a[mi*4+2]), "r"(a[mi*4+3]),
                          "r"(br[ni*2+0]), "r"(br[ni*2+1]));
                }
        }
    }

    // epilogue: logits + fused colsum(logits) partials
    float cs[8];
#pragma unroll
    for (int j = 0; j < 8; ++j) cs[j] = 0.f;

#pragma unroll
    for (int mi = 0; mi < 4; ++mi) {
        int r0 = m0 + wm * 64 + mi * 16 + (lane >> 2);
        float x20 = g_x2[r0], x21 = g_x2[r0 + 8];
#pragma unroll
        for (int ni = 0; ni < 4; ++ni) {
            int col = n0 + wn * 32 + ni * 8 + (lane & 3) * 2;
            float2 p2v = *(const float2*)&g_p2[col];
            float2 ga = __ldg((const float2*)(G + (size_t)r0 * K_PROTO + col));
            float2 gb = __ldg((const float2*)(G + (size_t)(r0 + 8) * K_PROTO + col));
            float2 o0, o1;
            o0.x = fmaf(2.f, d[mi][ni][0], ga.x) - x20 - p2v.x;
            o0.y = fmaf(2.f, d[mi][ni][1], ga.y) - x20 - p2v.y;
            o1.x = fmaf(2.f, d[mi][ni][2], gb.x) - x21 - p2v.x;
            o1.y = fmaf(2.f, d[mi][ni][3], gb.y) - x21 - p2v.y;
            *(float2*)(g_logits + (size_t)r0 * K_PROTO + col) = o0;
            *(float2*)(g_logits + (size_t)(r0 + 8) * K_PROTO + col) = o1;
            cs[ni * 2 + 0] += o0.x + o1.x;
            cs[ni * 2 + 1] += o0.y + o1.y;
        }
    }
    // reduce over the 8 lanes (lane>>2) that share each column
#pragma unroll
    for (int j = 0; j < 8; ++j) {
#pragma unroll
        for (int off = 4; off <= 16; off <<= 1)
            cs[j] += __shfl_xor_sync(0xffffffffu, cs[j], off);
    }
    if (lane < 4) {
        float* dst = g_vpart + (size_t)(blockIdx.y * 2 + wm) * K_PROTO;
#pragma unroll
        for (int j = 0; j < 8; ++j) {
            int col = n0 + wn * 32 + (j >> 1) * 8 + lane * 2 + (j & 1);
            dst[col] = cs[j];
        }
    }
}

// ===========================================================================
// K2: per-row softmax stats + argmax + gather + colsum(y) partials.
// ===========================================================================
__global__ void __launch_bounds__(256)
softmax_kernel(const float* __restrict__ P, float* __restrict__ out)
{
    const int b    = blockIdx.x;
    const int w    = threadIdx.x >> 5;
    const int lane = threadIdx.x & 31;

    float cy[32];
#pragma unroll
    for (int q = 0; q < 32; ++q) cy[q] = 0.f;
    float lsesum = 0.f;

    for (int i = 0; i < 16; ++i) {
        int row = b * 128 + w * 16 + i;
        const float4* L = (const float4*)(g_logits + (size_t)row * K_PROTO);
        float4 v[8];
#pragma unroll
        for (int j = 0; j < 8; ++j) v[j] = __ldg(&L[j * 32 + lane]);

        float m = -3.402823466e38f;
        int idx = 0;
#pragma unroll
        for (int j = 0; j < 8; ++j) {
            float* pv = (float*)&v[j];
#pragma unroll
            for (int tt = 0; tt < 4; ++tt) {
                float val = pv[tt];
                int k = j * 128 + lane * 4 + tt;
                if (val > m) { m = val; idx = k; }
            }
        }
#pragma unroll
        for (int off = 16; off; off >>= 1) {
            float om = __shfl_xor_sync(0xffffffffu, m, off);
            int   oi = __shfl_xor_sync(0xffffffffu, idx, off);
            if (om > m || (om == m && oi < idx)) { m = om; idx = oi; }
        }

        float s = 0.f;
#pragma unroll
        for (int j = 0; j < 8; ++j) {
            float* pv = (float*)&v[j];
#pragma unroll
            for (int tt = 0; tt < 4; ++tt) { pv[tt] = __expf(pv[tt] - m); s += pv[tt]; }
        }
#pragma unroll
        for (int off = 16; off; off >>= 1)
            s += __shfl_xor_sync(0xffffffffu, s, off);
        lsesum += m + __logf(s);
        float inv = 1.f / s;

#pragma unroll
        for (int j = 0; j < 8; ++j) {
            const float* pv = (const float*)&v[j];
#pragma unroll
            for (int tt = 0; tt < 4; ++tt)
                cy[j * 4 + tt] += pv[tt] * inv;
        }

        const float4* Pr = (const float4*)(P + (size_t)idx * D_DIM);
        float4* Or = (float4*)(out + (size_t)row * D_DIM);
        Or[lane]      = __ldg(&Pr[lane]);
        Or[lane + 32] = __ldg(&Pr[lane + 32]);
    }

    __shared__ float s_y[1024];
    __shared__ float s_lse[8];
    for (int q = threadIdx.x; q < 1024; q += 256) s_y[q] = 0.f;
    __syncthreads();
    for (int w2 = 0; w2 < 8; ++w2) {
        if (w == w2) {
#pragma unroll
            for (int j = 0; j < 8; ++j)
#pragma unroll
                for (int tt = 0; tt < 4; ++tt)
                    s_y[j * 128 + lane * 4 + tt] += cy[j * 4 + tt];
        }
        __syncthreads();
    }
    if (lane == 0) s_lse[w] = lsesum;
    __syncthreads();
    for (int q = threadIdx.x; q < 1024; q += 256)
        g_part_y[b * 1024 + q] = s_y[q];
    if (threadIdx.x == 0) {
        double t = 0.0;
        for (int q = 0; q < 8; ++q) t += (double)s_lse[q];
        g_part_lse[b] = t;
    }
}

// ===========================================================================
// K3: column reduce partials (double, deterministic)
// ===========================================================================
__global__ void colreduce_kernel()
{
    int k = blockIdx.x * 128 + threadIdx.x;
    double sy = 0.0;
    for (int bb = 0; bb < 256; ++bb)
        sy += (double)g_part_y[bb * 1024 + k];
    double sv = 0.0;
    for (int bb = 0; bb < 512; ++bb)
        sv += (double)g_vpart[(size_t)bb * 1024 + k];
    g_coly[k] = sy;
    g_colv[k] = sv;
}

// ===========================================================================
// K4: final scalar
// ===========================================================================
__global__ void final_kernel(float* __restrict__ out, int out_size)
{
    const int t = threadIdx.x;
    double lse_total = 0.0;
    for (int q = 0; q < 256; ++q) lse_total += g_part_lse[q];
    const double lse_mean = lse_total * (1.0 / N_ROWS);

    double t1 = 0.0, t2 = 0.0;
    for (int k = t; k < K_PROTO; k += 256) {
        double prior = g_coly[k] * (1.0 / N_ROWS) + 1e-6;
        double cmlp  = g_colv[k] * (1.0 / N_ROWS) - lse_mean;
        t1 += prior * log(prior);
        t2 += prior * cmlp;
    }
    __shared__ double r1[256];
    __shared__ double r2[256];
    r1[t] = t1; r2[t] = t2;
    __syncthreads();
    for (int off = 128; off; off >>= 1) {
        if (t < off) { r1[t] += r1[t + off]; r2[t] += r2[t + off]; }
        __syncthreads();
    }
    if (t == 0) {
        double capacity = r1[0] - r2[0];
        double ent      = -r1[0];
        out[out_size - 1] = (float)(capacity - 0.001 * ent);
    }
}

// ===========================================================================
extern "C" void kernel_launch(void* const* d_in, const int* in_sizes, int n_in,
                              void* d_out, int out_size)
{
    const float* X = (const float*)d_in[0];   // latents    [32768,256]
    const float* P = (const float*)d_in[1];   // prototypes [1024,256]
    const float* G = (const float*)d_in[2];   // gumbel     [32768,1024]
    float* out = (float*)d_out;

    cudaFuncSetAttribute(gemm_mma_kernel,
                         cudaFuncAttributeMaxDynamicSharedMemorySize, GEMM_SMEM);

    __nv_bfloat16 *xhi, *xlo, *phi, *plo;
    float *x2, *p2;
    cudaGetSymbolAddress((void**)&xhi, g_xhi);
    cudaGetSymbolAddress((void**)&xlo, g_xlo);
    cudaGetSymbolAddress((void**)&phi, g_phi);
    cudaGetSymbolAddress((void**)&plo, g_plo);
    cudaGetSymbolAddress((void**)&x2, g_x2);
    cudaGetSymbolAddress((void**)&p2, g_p2);

    prep_kernel<<<N_ROWS / 8, 256>>>(X, xhi, xlo, x2, N_ROWS);
    prep_kernel<<<K_PROTO / 8, 256>>>(P, phi, plo, p2, K_PROTO);
    gemm_mma_kernel<<<dim3(K_PROTO / NT, N_ROWS / MT), 512, GEMM_SMEM>>>(G);
    softmax_kernel<<<N_ROWS / 128, 256>>>(P, out);
    colreduce_kernel<<<K_PROTO / 128, 128>>>();
    final_kernel<<<1, 256>>>(out, out_size);
}